// round 16
// baseline (speedup 1.0000x reference)
#include <cuda_runtime.h>

#define NODES 7
#define CH 256
#define PAIRS 128
#define HID 128
#define P_TOTAL 65536
#define PF 8                    // prefetch depth (channel pairs per half)

typedef unsigned long long ull;

__device__ float g_nw[2 * NODES * CH];          // new_weight [b, n, c]
__device__ float g_attn[2 * NODES * P_TOTAL];   // attn scratch [b, n, p] (3.7MB)

// ---------------------------------------------------------------------------
__device__ __forceinline__ ull fma2(ull a, ull b, ull c) {
    ull d;
    asm("fma.rn.f32x2 %0, %1, %2, %3;" : "=l"(d) : "l"(a), "l"(b), "l"(c));
    return d;
}
__device__ __forceinline__ ull pack2(float x, float y) {
    ull r;
    asm("mov.b64 %0, {%1, %2};" : "=l"(r) : "f"(x), "f"(y));
    return r;
}
__device__ __forceinline__ void unpack2(ull v, float& x, float& y) {
    asm("mov.b64 {%0, %1}, %2;" : "=f"(x), "=f"(y) : "l"(v));
}
__device__ __forceinline__ float ldcs32(const float* p) {
    float v;
    asm volatile("ld.global.cs.b32 %0, [%1];" : "=f"(v) : "l"(p));
    return v;
}
__device__ __forceinline__ float4 ld128(const float* p) {
    float4 v;
    asm volatile("ld.global.v4.f32 {%0,%1,%2,%3}, [%4];"
                 : "=f"(v.x), "=f"(v.y), "=f"(v.z), "=f"(v.w) : "l"(p));
    return v;
}
__device__ __forceinline__ void stcs128(float* p, float4 v) {
    asm volatile("st.global.cs.v4.f32 [%0], {%1,%2,%3,%4};"
                 :: "l"(p), "f"(v.x), "f"(v.y), "f"(v.z), "f"(v.w));
}

// ---------------------------------------------------------------------------
// Pass 1: PURE READ stream (exact R8 champion).
// res (128MB) -> n1 -> softmax -> g_attn (plain stores, L2-resident).
// 2-way channel split: half h covers channels [128h, 128h+128) of one point.
// Blocks 0..1023 stream; blocks 1024..1037 compute the g_nw GEMM.
// ---------------------------------------------------------------------------
__global__ void __launch_bounds__(256, 4) pass1_kernel(
    const float* __restrict__ inp,     // [1,2,7,128]
    const float* __restrict__ res,     // [2, 256, 65536]
    const float* __restrict__ Wres,    // [256, 7]
    const float* __restrict__ nfh,     // [128,1]
    const float* __restrict__ weight)  // [128, 256]
{
    const int tid = threadIdx.x;
    const int bid = blockIdx.x;

    // ---- tail blocks: new_weight GEMM ----
    if (bid >= 1024) {
        const int bn = bid - 1024;       // 0..13 = b*7+n
        float acc = 0.f;
#pragma unroll 16
        for (int h = 0; h < HID; ++h)
            acc += __ldg(inp + bn * HID + h) * weight[h * CH + tid];
        g_nw[bn * CH + tid] = acc;
        return;
    }

    __shared__ ull W2[PAIRS][8];          // (w[2k][n], w[2k+1][n])
    __shared__ float part[NODES][2][128]; // cross-half partials
    __shared__ float sh_n2[8];

    const int half = tid >> 7;           // channel half
    const int pl   = tid & 127;
    const int b    = bid >> 9;           // 0..1
    const int tile = bid & 511;
    const int p    = tile * 128 + pl;
    const int wid  = tid >> 5;
    const int lane = tid & 31;

    // n2[b][n]: warp n computes the 128-dot via shuffle
    if (wid < NODES) {
        float s = 0.f;
#pragma unroll
        for (int i = 0; i < 4; ++i) {
            int h = lane + 32 * i;
            s += __ldg(inp + b * NODES * HID + wid * HID + h) * __ldg(nfh + h);
        }
#pragma unroll
        for (int o = 16; o; o >>= 1)
            s += __shfl_xor_sync(0xffffffffu, s, o);
        if (lane == 0) sh_n2[wid] = s;
    }
    if (tid < PAIRS) {
        const int k = tid;
#pragma unroll
        for (int n = 0; n < NODES; ++n) {
            float w0 = Wres[(2 * k) * NODES + n];
            float w1 = Wres[(2 * k + 1) * NODES + n];
            W2[k][n] = pack2(w0, w1);
        }
        W2[k][7] = 0ull;
    }
    __syncthreads();

    float n2s[NODES];
#pragma unroll
    for (int n = 0; n < NODES; ++n) n2s[n] = sh_n2[n];

    const int kbase = half * 64;
    const float* rfp = res + (size_t)b * CH * P_TOTAL
                           + (size_t)(half * 128) * P_TOTAL + p;

    ull acc[NODES];
#pragma unroll
    for (int n = 0; n < NODES; ++n) acc[n] = 0ull;

    float a0[PF], a1[PF];
#pragma unroll
    for (int i = 0; i < PF; ++i) {
        a0[i] = ldcs32(rfp + (size_t)(2 * i) * P_TOTAL);
        a1[i] = ldcs32(rfp + (size_t)(2 * i + 1) * P_TOTAL);
    }

#pragma unroll 1
    for (int jb = 0; jb < 64; jb += PF) {
#pragma unroll
        for (int i = 0; i < PF; ++i) {
            ull v = pack2(a0[i], a1[i]);
            if (jb + PF < 64) {
                a0[i] = ldcs32(rfp + (size_t)(2 * (jb + PF + i)) * P_TOTAL);
                a1[i] = ldcs32(rfp + (size_t)(2 * (jb + PF + i) + 1) * P_TOTAL);
            }
            const ulonglong2* wr = (const ulonglong2*)(&W2[kbase + jb + i][0]);
            ulonglong2 w01 = wr[0];
            ulonglong2 w23 = wr[1];
            ulonglong2 w45 = wr[2];
            ulonglong2 w6p = wr[3];
            acc[0] = fma2(v, w01.x, acc[0]);
            acc[1] = fma2(v, w01.y, acc[1]);
            acc[2] = fma2(v, w23.x, acc[2]);
            acc[3] = fma2(v, w23.y, acc[3]);
            acc[4] = fma2(v, w45.x, acc[4]);
            acc[5] = fma2(v, w45.y, acc[5]);
            acc[6] = fma2(v, w6p.x, acc[6]);
        }
    }

    // Exchange partials between halves
    float myp[NODES];
#pragma unroll
    for (int n = 0; n < NODES; ++n) {
        float lo, hi;
        unpack2(acc[n], lo, hi);
        myp[n] = lo + hi;
        part[n][half][pl] = myp[n];
    }
    __syncthreads();

    float s[NODES];
#pragma unroll
    for (int n = 0; n < NODES; ++n)
        s[n] = myp[n] + part[n][half ^ 1][pl] + n2s[n];

    float m = s[0];
#pragma unroll
    for (int n = 1; n < NODES; ++n) m = fmaxf(m, s[n]);
    float e[NODES], sum = 0.f;
#pragma unroll
    for (int n = 0; n < NODES; ++n) { e[n] = __expf(s[n] - m); sum += e[n]; }
    float inv = __fdividef(1.f, sum);

    // Split attn stores: half0 -> nodes 0..3, half1 -> nodes 4..6 (plain st)
    if (half == 0) {
#pragma unroll
        for (int n = 0; n < 4; ++n)
            g_attn[(b * NODES + n) * P_TOTAL + p] = e[n] * inv;
    } else {
#pragma unroll
        for (int n = 4; n < NODES; ++n)
            g_attn[(b * NODES + n) * P_TOTAL + p] = e[n] * inv;
    }
}

// ---------------------------------------------------------------------------
// Pass 2: PURE WRITE stream, slimmed. g_attn (L2) + g_nw -> out (128MB).
// 4 points/thread, 4-way channel split, STG.128. 512 blocks x 256 threads.
// Per thread: 7 x LDG.128 attn (contiguous), 64 channels x
//             (1 LDS row + 14 fma2 + 1 STG.128).
// ---------------------------------------------------------------------------
__global__ void __launch_bounds__(256, 6) pass2_kernel(
    float* __restrict__ out)           // [2, 256, 65536]
{
    cudaGridDependencySynchronize();   // PDL guard: pass1 memory visible

    __shared__ ull NW[CH][8];          // (nw[n][c], nw[n][c]) duplicated

    const int tid     = threadIdx.x;
    const int quarter = tid >> 6;       // 0..3 channel quarter
    const int pg      = tid & 63;
    const int b       = blockIdx.x >> 8;   // 0..1 (256 blocks per batch)
    const int tile    = blockIdx.x & 255;
    const int p0      = tile * 256 + pg * 4;   // 4 consecutive points

    {
        const int c = tid;
#pragma unroll
        for (int n = 0; n < NODES; ++n) {
            float q = g_nw[(b * NODES + n) * CH + c];
            NW[c][n] = pack2(q, q);
        }
        NW[c][7] = 0ull;
    }
    __syncthreads();

    // attn for 4 points: 7 contiguous LDG.128 (L2 hits)
    ull at01[NODES], at23[NODES];
#pragma unroll
    for (int n = 0; n < NODES; ++n) {
        float4 a = ld128(&g_attn[(b * NODES + n) * P_TOTAL + p0]);
        at01[n] = pack2(a.x, a.y);
        at23[n] = pack2(a.z, a.w);
    }

    const int cbase = quarter * 64;
    float* op = out + (size_t)b * CH * P_TOTAL + (size_t)cbase * P_TOTAL + p0;
#pragma unroll 4
    for (int j = 0; j < 64; ++j) {
        const ulonglong2* nr = (const ulonglong2*)(&NW[cbase + j][0]);
        ulonglong2 q01 = nr[0];
        ulonglong2 q23 = nr[1];
        ulonglong2 q45 = nr[2];
        ulonglong2 q6p = nr[3];
        ull o01 = 0ull, o23 = 0ull;
        o01 = fma2(at01[0], q01.x, o01);  o23 = fma2(at23[0], q01.x, o23);
        o01 = fma2(at01[1], q01.y, o01);  o23 = fma2(at23[1], q01.y, o23);
        o01 = fma2(at01[2], q23.x, o01);  o23 = fma2(at23[2], q23.x, o23);
        o01 = fma2(at01[3], q23.y, o01);  o23 = fma2(at23[3], q23.y, o23);
        o01 = fma2(at01[4], q45.x, o01);  o23 = fma2(at23[4], q45.x, o23);
        o01 = fma2(at01[5], q45.y, o01);  o23 = fma2(at23[5], q45.y, o23);
        o01 = fma2(at01[6], q6p.x, o01);  o23 = fma2(at23[6], q6p.x, o23);
        float4 ov;
        unpack2(o01, ov.x, ov.y);
        unpack2(o23, ov.z, ov.w);
        ov.x = fmaxf(ov.x, 0.f);
        ov.y = fmaxf(ov.y, 0.f);
        ov.z = fmaxf(ov.z, 0.f);
        ov.w = fmaxf(ov.w, 0.f);
        stcs128(op + (size_t)j * P_TOTAL, ov);
    }
}

// ---------------------------------------------------------------------------
extern "C" void kernel_launch(void* const* d_in, const int* in_sizes, int n_in,
                              void* d_out, int out_size) {
    const float* inp    = (const float*)d_in[0];  // [1,2,7,128]
    const float* res    = (const float*)d_in[1];  // [2,256,16,64,64]
    const float* Wres   = (const float*)d_in[2];  // [256,7]
    const float* nfh    = (const float*)d_in[3];  // [128,1]
    const float* weight = (const float*)d_in[4];  // [128,256]

    pass1_kernel<<<1038, 256>>>(inp, res, Wres, nfh, weight);

    // pass2 with PDL: overlap launch/scheduling with pass1's tail.
    cudaLaunchConfig_t cfg = {};
    cfg.gridDim  = dim3(512, 1, 1);
    cfg.blockDim = dim3(256, 1, 1);
    cudaLaunchAttribute attrs[1];
    attrs[0].id = cudaLaunchAttributeProgrammaticStreamSerialization;
    attrs[0].val.programmaticStreamSerializationAllowed = 1;
    cfg.attrs = attrs;
    cfg.numAttrs = 1;
    cudaLaunchKernelEx(&cfg, pass2_kernel, (float*)d_out);
}

// round 17
// speedup vs baseline: 1.1475x; 1.1475x over previous
#include <cuda_runtime.h>

#define NODES 7
#define CH 256
#define PAIRS 128
#define HID 128
#define P_TOTAL 65536
#define PF 8                    // prefetch depth (channel pairs per half)

typedef unsigned long long ull;

__device__ float g_nw[2 * NODES * CH];          // new_weight [b, n, c]
__device__ float g_attn[2 * NODES * P_TOTAL];   // attn scratch [b, n, p] (3.7MB)

// ---------------------------------------------------------------------------
__device__ __forceinline__ ull fma2(ull a, ull b, ull c) {
    ull d;
    asm("fma.rn.f32x2 %0, %1, %2, %3;" : "=l"(d) : "l"(a), "l"(b), "l"(c));
    return d;
}
__device__ __forceinline__ ull pack2(float x, float y) {
    ull r;
    asm("mov.b64 %0, {%1, %2};" : "=l"(r) : "f"(x), "f"(y));
    return r;
}
__device__ __forceinline__ void unpack2(ull v, float& x, float& y) {
    asm("mov.b64 {%0, %1}, %2;" : "=f"(x), "=f"(y) : "l"(v));
}
__device__ __forceinline__ float ldcs32(const float* p) {
    float v;
    asm volatile("ld.global.cs.b32 %0, [%1];" : "=f"(v) : "l"(p));
    return v;
}
__device__ __forceinline__ ull ldg64(const float* p) {
    ull v;
    asm volatile("ld.global.b64 %0, [%1];" : "=l"(v) : "l"(p));
    return v;
}
__device__ __forceinline__ void st64(float* p, ull v) {
    // plain write-back store: completes on L2 acceptance; dirty lines drain
    // lazily, overlapping the next replay's read stream.
    asm volatile("st.global.b64 [%0], %1;" :: "l"(p), "l"(v));
}

// ---------------------------------------------------------------------------
// Pass 1: PURE READ stream (exact R8 champion).
// res (128MB) -> n1 -> softmax -> g_attn (plain stores, L2-resident).
// 2-way channel split: half h covers channels [128h, 128h+128) of one point.
// Blocks 0..1023 stream; blocks 1024..1037 compute the g_nw GEMM.
// ---------------------------------------------------------------------------
__global__ void __launch_bounds__(256, 4) pass1_kernel(
    const float* __restrict__ inp,     // [1,2,7,128]
    const float* __restrict__ res,     // [2, 256, 65536]
    const float* __restrict__ Wres,    // [256, 7]
    const float* __restrict__ nfh,     // [128,1]
    const float* __restrict__ weight)  // [128, 256]
{
    const int tid = threadIdx.x;
    const int bid = blockIdx.x;

    // ---- tail blocks: new_weight GEMM ----
    if (bid >= 1024) {
        const int bn = bid - 1024;       // 0..13 = b*7+n
        float acc = 0.f;
#pragma unroll 16
        for (int h = 0; h < HID; ++h)
            acc += __ldg(inp + bn * HID + h) * weight[h * CH + tid];
        g_nw[bn * CH + tid] = acc;
        return;
    }

    __shared__ ull W2[PAIRS][8];          // (w[2k][n], w[2k+1][n])
    __shared__ float part[NODES][2][128]; // cross-half partials
    __shared__ float sh_n2[8];

    const int half = tid >> 7;           // channel half
    const int pl   = tid & 127;
    const int b    = bid >> 9;           // 0..1
    const int tile = bid & 511;
    const int p    = tile * 128 + pl;
    const int wid  = tid >> 5;
    const int lane = tid & 31;

    // n2[b][n]: warp n computes the 128-dot via shuffle
    if (wid < NODES) {
        float s = 0.f;
#pragma unroll
        for (int i = 0; i < 4; ++i) {
            int h = lane + 32 * i;
            s += __ldg(inp + b * NODES * HID + wid * HID + h) * __ldg(nfh + h);
        }
#pragma unroll
        for (int o = 16; o; o >>= 1)
            s += __shfl_xor_sync(0xffffffffu, s, o);
        if (lane == 0) sh_n2[wid] = s;
    }
    if (tid < PAIRS) {
        const int k = tid;
#pragma unroll
        for (int n = 0; n < NODES; ++n) {
            float w0 = Wres[(2 * k) * NODES + n];
            float w1 = Wres[(2 * k + 1) * NODES + n];
            W2[k][n] = pack2(w0, w1);
        }
        W2[k][7] = 0ull;
    }
    __syncthreads();

    float n2s[NODES];
#pragma unroll
    for (int n = 0; n < NODES; ++n) n2s[n] = sh_n2[n];

    const int kbase = half * 64;
    const float* rfp = res + (size_t)b * CH * P_TOTAL
                           + (size_t)(half * 128) * P_TOTAL + p;

    ull acc[NODES];
#pragma unroll
    for (int n = 0; n < NODES; ++n) acc[n] = 0ull;

    float a0[PF], a1[PF];
#pragma unroll
    for (int i = 0; i < PF; ++i) {
        a0[i] = ldcs32(rfp + (size_t)(2 * i) * P_TOTAL);
        a1[i] = ldcs32(rfp + (size_t)(2 * i + 1) * P_TOTAL);
    }

#pragma unroll 1
    for (int jb = 0; jb < 64; jb += PF) {
#pragma unroll
        for (int i = 0; i < PF; ++i) {
            ull v = pack2(a0[i], a1[i]);
            if (jb + PF < 64) {
                a0[i] = ldcs32(rfp + (size_t)(2 * (jb + PF + i)) * P_TOTAL);
                a1[i] = ldcs32(rfp + (size_t)(2 * (jb + PF + i) + 1) * P_TOTAL);
            }
            const ulonglong2* wr = (const ulonglong2*)(&W2[kbase + jb + i][0]);
            ulonglong2 w01 = wr[0];
            ulonglong2 w23 = wr[1];
            ulonglong2 w45 = wr[2];
            ulonglong2 w6p = wr[3];
            acc[0] = fma2(v, w01.x, acc[0]);
            acc[1] = fma2(v, w01.y, acc[1]);
            acc[2] = fma2(v, w23.x, acc[2]);
            acc[3] = fma2(v, w23.y, acc[3]);
            acc[4] = fma2(v, w45.x, acc[4]);
            acc[5] = fma2(v, w45.y, acc[5]);
            acc[6] = fma2(v, w6p.x, acc[6]);
        }
    }

    // Exchange partials between halves
    float myp[NODES];
#pragma unroll
    for (int n = 0; n < NODES; ++n) {
        float lo, hi;
        unpack2(acc[n], lo, hi);
        myp[n] = lo + hi;
        part[n][half][pl] = myp[n];
    }
    __syncthreads();

    float s[NODES];
#pragma unroll
    for (int n = 0; n < NODES; ++n)
        s[n] = myp[n] + part[n][half ^ 1][pl] + n2s[n];

    float m = s[0];
#pragma unroll
    for (int n = 1; n < NODES; ++n) m = fmaxf(m, s[n]);
    float e[NODES], sum = 0.f;
#pragma unroll
    for (int n = 0; n < NODES; ++n) { e[n] = __expf(s[n] - m); sum += e[n]; }
    float inv = __fdividef(1.f, sum);

    // Split attn stores: half0 -> nodes 0..3, half1 -> nodes 4..6 (plain st)
    if (half == 0) {
#pragma unroll
        for (int n = 0; n < 4; ++n)
            g_attn[(b * NODES + n) * P_TOTAL + p] = e[n] * inv;
    } else {
#pragma unroll
        for (int n = 4; n < NODES; ++n)
            g_attn[(b * NODES + n) * P_TOTAL + p] = e[n] * inv;
    }
}

// ---------------------------------------------------------------------------
// Pass 2: write stream (exact R8 shape; plain write-back stores).
// g_attn (L2) + g_nw -> out (128MB). 2 points/thread, 256 blocks x 256 thr.
// ---------------------------------------------------------------------------
__global__ void __launch_bounds__(256, 6) pass2_kernel(
    float* __restrict__ out)           // [2, 256, 65536]
{
    __shared__ ull NW[CH][8];

    const int tid  = threadIdx.x;
    const int b    = blockIdx.x >> 7;
    const int tile = blockIdx.x & 127;

    {
        const int c = tid;
#pragma unroll
        for (int n = 0; n < NODES; ++n) {
            float q = g_nw[(b * NODES + n) * CH + c];
            NW[c][n] = pack2(q, q);
        }
        NW[c][7] = 0ull;
    }
    __syncthreads();

    const int p0 = tile * 512 + 2 * tid;

    ull at[NODES];
#pragma unroll
    for (int n = 0; n < NODES; ++n)
        at[n] = ldg64(&g_attn[(b * NODES + n) * P_TOTAL + p0]);

    float* op = out + (size_t)b * CH * P_TOTAL + p0;
#pragma unroll 4
    for (int c = 0; c < CH; ++c) {
        const ulonglong2* nr = (const ulonglong2*)(&NW[c][0]);
        ulonglong2 q01 = nr[0];
        ulonglong2 q23 = nr[1];
        ulonglong2 q45 = nr[2];
        ulonglong2 q6p = nr[3];
        ull o = 0ull;
        o = fma2(at[0], q01.x, o);
        o = fma2(at[1], q01.y, o);
        o = fma2(at[2], q23.x, o);
        o = fma2(at[3], q23.y, o);
        o = fma2(at[4], q45.x, o);
        o = fma2(at[5], q45.y, o);
        o = fma2(at[6], q6p.x, o);
        float v0, v1;
        unpack2(o, v0, v1);
        st64(op + (size_t)c * P_TOTAL, pack2(fmaxf(v0, 0.f), fmaxf(v1, 0.f)));
    }
}

// ---------------------------------------------------------------------------
extern "C" void kernel_launch(void* const* d_in, const int* in_sizes, int n_in,
                              void* d_out, int out_size) {
    const float* inp    = (const float*)d_in[0];  // [1,2,7,128]
    const float* res    = (const float*)d_in[1];  // [2,256,16,64,64]
    const float* Wres   = (const float*)d_in[2];  // [256,7]
    const float* nfh    = (const float*)d_in[3];  // [128,1]
    const float* weight = (const float*)d_in[4];  // [128,256]

    pass1_kernel<<<1038, 256>>>(inp, res, Wres, nfh, weight);
    pass2_kernel<<<256, 256>>>((float*)d_out);
}